// round 9
// baseline (speedup 1.0000x reference)
#include <cuda_runtime.h>

// CRF loss via BIDIRECTIONAL scaled forward algorithm with split dot products.
// One 256-thread CTA per batch row:
//   tids   0..127 (warps 0-3): alpha forward,  t = 0 .. m
//   tids 128..255 (warps 4-7): beta  backward, t = len-1 .. m
// Z = sum_i alpha_m[i]*beta_m[i]. Each group has its own named barrier
// (bar.sync id,128) and tight loop. Within a group, thread pair (col, r)
// computes a 28-term half of the 50-term dot product; halves combined with
// one shfl_xor. Exact pow-2 rescaling each step (pivot = max P[1..3]).
// Backward's final step (excluding ef_m) is peeled.

constexpr int TT = 50;    // tags
constexpr int LL = 256;   // max length
constexpr int NTH = 256;
constexpr int STARTT = TT - 2;
constexpr int STOPT  = TT - 1;

#define LOG2E 1.4426950408889634f
#define LN2F  0.6931471805599453f

__device__ float    g_partial[1024];
__device__ unsigned g_done = 0;

__device__ __forceinline__ float ex2(float x) {
    float r;
    asm("ex2.approx.ftz.f32 %0, %1;" : "=f"(r) : "f"(x));
    return r;
}

__device__ __forceinline__ void barg(int id) {    // group barrier, 128 threads
    asm volatile("bar.sync %0, 128;" :: "r"(id));
}

__device__ __forceinline__ float blockSum(float v, volatile float* red) {
#pragma unroll
    for (int o = 16; o; o >>= 1) v += __shfl_xor_sync(0xffffffffu, v, o);
    if ((threadIdx.x & 31) == 0) red[threadIdx.x >> 5] = v;
    __syncthreads();
    v = ((red[0] + red[1]) + (red[2] + red[3]))
      + ((red[4] + red[5]) + (red[6] + red[7]));
    __syncthreads();
    return v;
}

__global__ void __launch_bounds__(NTH, 1)
crf_kernel(const float* __restrict__ feats, const float* __restrict__ trans,
           const int* __restrict__ tags, const int* __restrict__ mask,
           float* __restrict__ out) {
    __shared__ __align__(16) float Ab[2][64];   // alpha ping-pong
    __shared__ __align__(16) float Bb[2][64];   // beta  ping-pong
    __shared__ float red[8];
    __shared__ int s_len, s_kf, s_kb;
    __shared__ unsigned s_rank;

    const int b    = blockIdx.x;
    const int tid  = threadIdx.x;
    const bool isF = (tid < 128);
    const int gt   = tid & 127;        // thread index within group
    const int col  = gt >> 1;          // state/output column 0..63
    const int r    = gt & 1;           // half index
    const bool cv  = (col < TT);
    const int cc   = cv ? col : (TT - 1);
    const int bid  = isF ? 1 : 2;
    const int i0   = r * 28;           // start of my 28-term half

    if (tid == 0) s_len = 0;
    __syncthreads();

    // ---- sequence length (mask is a 0/1 prefix) ----
    {
        int m = mask[(size_t)b * LL + tid];
        int c = __popc(__ballot_sync(0xffffffffu, m != 0));
        if ((tid & 31) == 0) atomicAdd(&s_len, c);
    }

    // ---- E half in registers:
    //   forward  pair (col,r): E[i] = exp(trans[i0+i][col])   (column slice)
    //   backward pair (col,r): E[i] = exp(trans[col][i0+i])   (row slice)
    float E[28];
    {
        const float* tb = isF ? (trans + cc) : (trans + cc * TT);
        const int    ts = isF ? TT : 1;
#pragma unroll
        for (int i = 0; i < 28; i++) {
            int gi = i0 + i;
            float e = 0.f;
            if (gi < TT && cv) e = ex2(tb[gi * ts] * LOG2E);
            E[i] = e;
        }
    }

    const float* fb = feats + (size_t)b * LL * TT;
    const float s0   = trans[STARTT * TT + 1];
    const float tref = trans[1 * TT + STOPT];
    const float C2f  = s0 * LOG2E;

    __syncthreads();
    const int len = s_len;
    const int nf  = (len - 1) >> 1;        // forward steps
    const int nb  = (len - 1) - nf;        // backward steps (>= nf)

    // ---- group inits (r==0 writes all 64 cols incl. zero pads) ----
    if (r == 0) {
        if (isF) {
            float p = cv ? ex2((fb[cc] + trans[STARTT * TT + cc] - s0) * LOG2E)
                         : 0.f;
            Ab[0][col] = p;
        } else {
            float w = cv ? ex2((trans[cc * TT + STOPT] - tref) * LOG2E) : 0.f;
            float f = (nb > 0) ? ex2(fb[(len - 1) * TT + cc] * LOG2E) : 1.f;
            Bb[0][col] = cv ? w * f : 0.f;
        }
    }
    int kacc = 0;

    // ---- distance-2 feats prefetch (clamped, branch-free) ----
    int r1 = isF ? 1 : len - 2;
    int r2 = isF ? 2 : len - 3;
    r1 = min(max(r1, 0), len - 1);
    r2 = min(max(r2, 0), len - 1);
    float fc = fb[r1 * TT + cc];
    float fn = fb[r2 * TT + cc];

    float* Pc = isF ? Ab[0] : Bb[0];
    float* Pn = isF ? Ab[1] : Bb[1];
    barg(bid);

    // one recurrence step: half dot product + shfl combine + scaled store
#define CRF_STEP(EFV)                                                     \
    {                                                                     \
        const float4* pp = (const float4*)Pc;                             \
        float4 v0 = pp[0];                                                \
        float m = fmaxf(fmaxf(v0.y, v0.z), v0.w);                         \
        int   k = (__float_as_int(m) >> 23) - 127;                        \
        float sf = __int_as_float((127 - k) << 23) * (EFV);               \
        const float4* p4 = (const float4*)(Pc + i0);                      \
        float a0, a1, a2, a3;                                             \
        {                                                                 \
            float4 v = p4[0];                                             \
            a0 = v.x * E[0]; a1 = v.y * E[1];                             \
            a2 = v.z * E[2]; a3 = v.w * E[3];                             \
        }                                                                 \
        _Pragma("unroll")                                                 \
        for (int q = 1; q < 7; q++) {                                     \
            float4 v = p4[q];                                             \
            a0 = fmaf(v.x, E[4 * q + 0], a0);                             \
            a1 = fmaf(v.y, E[4 * q + 1], a1);                             \
            a2 = fmaf(v.z, E[4 * q + 2], a2);                             \
            a3 = fmaf(v.w, E[4 * q + 3], a3);                             \
        }                                                                 \
        float half = (a0 + a1) + (a2 + a3);                               \
        float sres = half + __shfl_xor_sync(0xffffffffu, half, 1);        \
        if (r == 0) Pn[col] = sres * sf;                                  \
        kacc += k;                                                        \
        barg(bid);                                                        \
        float* _t = Pc; Pc = Pn; Pn = _t;                                 \
    }

    if (isF) {
        for (int s = 1; s <= nf; ++s) {
            float efv = ex2(fc * LOG2E);
            fc = fn;
            int rn = min(s + 2, len - 1);
            fn = fb[rn * TT + cc];
            CRF_STEP(efv);
        }
    } else {
        for (int s = 1; s < nb; ++s) {
            float efv = ex2(fc * LOG2E);
            fc = fn;
            int rn = max(len - 3 - s, 0);
            fn = fb[rn * TT + cc];
            CRF_STEP(efv);
        }
        if (nb >= 1) {                  // final step: exclude ef_m
            CRF_STEP(1.0f);
        }
    }
#undef CRF_STEP

    // ---- combine at the midpoint: Z = sum_i alpha_m[i] * beta_m[i] ----
    if (tid == 0)   s_kf = kacc;
    if (tid == 128) s_kb = kacc;
    __syncthreads();
    float z = 0.f;
    if (isF && cv && r == 0) z = Pc[col] * Bb[nb & 1][col];
    float sumv = blockSum(z, red);
    float fwd = (log2f(sumv) + C2f + (float)(s_kf + s_kb)) * LN2F + tref;

    // ---- gold score ----
    const int* tgb = tags + (size_t)b * LL;
    float gl = 0.f;
    if (tid < len) {
        int tg = tgb[tid];
        int pv = (tid == 0) ? STARTT : tgb[tid - 1];
        gl = fb[tid * TT + tg] + trans[pv * TT + tg];
    }
    float gold = blockSum(gl, red);

    if (tid == 0) {
        gold += trans[tgb[len - 1] * TT + STOPT];
        g_partial[b] = fwd - gold;
    }

    // ---- fused finalize: last CTA sums all partials (fixed order) ----
    __threadfence();
    if (tid == 0) s_rank = atomicAdd(&g_done, 1u);
    __syncthreads();
    if (s_rank == gridDim.x - 1) {
        const int B = gridDim.x;
        if (tid < 32) {
            float acc = 0.f;
            for (int i = tid; i < B; i += 32) {
                float v;
                asm volatile("ld.global.cg.f32 %0, [%1];" : "=f"(v)
                             : "l"(&g_partial[i]));
                acc += v;
            }
#pragma unroll
            for (int o = 16; o; o >>= 1)
                acc += __shfl_xor_sync(0xffffffffu, acc, o);
            if (tid == 0) {
                *out = acc;
                g_done = 0;   // reset for next graph replay
            }
        }
    }
}

extern "C" void kernel_launch(void* const* d_in, const int* in_sizes, int n_in,
                              void* d_out, int out_size) {
    const float* feats = (const float*)d_in[0];
    const float* trans = (const float*)d_in[1];
    const int*   tags  = (const int*)d_in[2];
    const int*   mask  = (const int*)d_in[3];
    int B = in_sizes[0] / (LL * TT);

    crf_kernel<<<B, NTH>>>(feats, trans, tags, mask, (float*)d_out);
}